// round 13
// baseline (speedup 1.0000x reference)
#include <cuda_runtime.h>
#include <math.h>
#include <stdint.h>

// ConfidenceCalibration: softmax over bins sums to 1 =>
//   final = clip(sigmoid(mean(x,-1)) * bin_scaling[bucketize(base)], 0, 1)
// Pure HBM read of x (128 MB) + tiny epilogue.
//
// R12 -> R13: CTA-size sweep is monotone: DRAM% 57.6 (512thr) -> 70.4
// (256thr) -> 71.4 (128thr), kernel dur 30.1 -> 24.6 -> 24.3 us. Mechanism:
// CTA size sets the synchronized front-batched LDG burst depth into the
// per-SM L1tex queue. Continue: 64-thread CTAs (16-LDG bursts, 16384 CTAs,
// still full occupancy at 32 CTAs/SM).

__device__ __forceinline__ uint64_t pack_f32x2(float lo, float hi) {
    uint64_t r;
    asm("mov.b64 %0, {%1, %2};" : "=l"(r) : "f"(lo), "f"(hi));
    return r;
}
__device__ __forceinline__ uint64_t add_f32x2(uint64_t a, uint64_t b) {
    uint64_t r;
    asm("add.rn.f32x2 %0, %1, %2;" : "=l"(r) : "l"(a), "l"(b));
    return r;
}
__device__ __forceinline__ float hsum_f32x2(uint64_t a) {
    float lo, hi;
    asm("mov.b64 {%0, %1}, %2;" : "=f"(lo), "=f"(hi) : "l"(a));
    return lo + hi;
}

__device__ __forceinline__ float warp_reduce_sum(float s) {
    #pragma unroll
    for (int o = 16; o; o >>= 1) s += __shfl_xor_sync(0xffffffffu, s, o);
    return s;
}

__device__ __forceinline__ void finalize(float s, float invD, int NB,
                                         const float* __restrict__ bin_scaling,
                                         float* __restrict__ out, int row) {
    float mean = s * invD;
    float base = 1.0f / (1.0f + expf(-mean));
    // searchsorted(linspace(0,1,NB+1), base, 'right') - 1
    int idx = -1;
    for (int i = 0; i <= NB; i++) {
        float bnd = (float)i / (float)NB;
        if (bnd <= base) idx = i; else break;
    }
    float scale = (idx >= 0 && idx < NB) ? bin_scaling[idx] : 0.0f;
    out[row] = fminf(fmaxf(base * scale, 0.0f), 1.0f);
}

// Specialized: D == 1024. One row per warp, 8x LDG.128 front-batched,
// packed f32x2 reduction tree. 64-thread CTAs (minimal load bursts).
__global__ void __launch_bounds__(64) confcal_kernel_1024(
        const float* __restrict__ x,
        const float* __restrict__ bin_scaling,
        float* __restrict__ out,
        int B, int NB) {
    const int gwarp = (blockIdx.x * blockDim.x + threadIdx.x) >> 5;
    const int lane  = threadIdx.x & 31;
    if (gwarp >= B) return;

    const float4* p = reinterpret_cast<const float4*>(x + (size_t)gwarp * 1024u) + lane;

    // 8 independent streaming loads, all in flight before arithmetic.
    float4 v0 = __ldcs(p + 0 * 32);
    float4 v1 = __ldcs(p + 1 * 32);
    float4 v2 = __ldcs(p + 2 * 32);
    float4 v3 = __ldcs(p + 3 * 32);
    float4 v4 = __ldcs(p + 4 * 32);
    float4 v5 = __ldcs(p + 5 * 32);
    float4 v6 = __ldcs(p + 6 * 32);
    float4 v7 = __ldcs(p + 7 * 32);

    // Packed f32x2 pairwise tree: 16 packs, 15 packed adds, 1 scalar add.
    uint64_t p0 = add_f32x2(pack_f32x2(v0.x, v0.y), pack_f32x2(v0.z, v0.w));
    uint64_t p1 = add_f32x2(pack_f32x2(v1.x, v1.y), pack_f32x2(v1.z, v1.w));
    uint64_t p2 = add_f32x2(pack_f32x2(v2.x, v2.y), pack_f32x2(v2.z, v2.w));
    uint64_t p3 = add_f32x2(pack_f32x2(v3.x, v3.y), pack_f32x2(v3.z, v3.w));
    uint64_t p4 = add_f32x2(pack_f32x2(v4.x, v4.y), pack_f32x2(v4.z, v4.w));
    uint64_t p5 = add_f32x2(pack_f32x2(v5.x, v5.y), pack_f32x2(v5.z, v5.w));
    uint64_t p6 = add_f32x2(pack_f32x2(v6.x, v6.y), pack_f32x2(v6.z, v6.w));
    uint64_t p7 = add_f32x2(pack_f32x2(v7.x, v7.y), pack_f32x2(v7.z, v7.w));
    uint64_t q0 = add_f32x2(add_f32x2(p0, p1), add_f32x2(p2, p3));
    uint64_t q1 = add_f32x2(add_f32x2(p4, p5), add_f32x2(p6, p7));
    float s = hsum_f32x2(add_f32x2(q0, q1));

    s = warp_reduce_sum(s);
    if (lane == 0) finalize(s, 1.0f / 1024.0f, NB, bin_scaling, out, gwarp);
}

// Generic fallback for other D
__global__ void confcal_kernel_gen(const float* __restrict__ x,
                                   const float* __restrict__ bin_scaling,
                                   float* __restrict__ out,
                                   int B, int D, int NB) {
    const int gwarp = (blockIdx.x * blockDim.x + threadIdx.x) >> 5;
    const int lane  = threadIdx.x & 31;
    if (gwarp >= B) return;

    const float* rowp = x + (size_t)gwarp * (size_t)D;
    const int nvec = D >> 2;
    const float4* row4 = reinterpret_cast<const float4*>(rowp);

    float s = 0.0f;
    #pragma unroll 8
    for (int i = lane; i < nvec; i += 32) {
        float4 v = __ldcs(row4 + i);
        s += (v.x + v.y) + (v.z + v.w);
    }
    for (int i = (nvec << 2) + lane; i < D; i += 32) s += rowp[i];

    s = warp_reduce_sum(s);
    if (lane == 0) finalize(s, 1.0f / (float)D, NB, bin_scaling, out, gwarp);
}

extern "C" void kernel_launch(void* const* d_in, const int* in_sizes, int n_in,
                              void* d_out, int out_size) {
    const float* x           = (const float*)d_in[0];
    const float* bin_scaling = (const float*)d_in[7];
    float* out = (float*)d_out;

    const int B  = out_size;            // 32768
    const int D  = in_sizes[0] / B;     // 1024
    const int NB = in_sizes[7];         // 15

    if (D == 1024 && (((uintptr_t)x) & 15u) == 0) {
        const int threads = 64;         // 2 warps = 2 rows per block
        const int rows_per_block = threads / 32;
        const int blocks = (B + rows_per_block - 1) / rows_per_block;   // 16384
        confcal_kernel_1024<<<blocks, threads>>>(x, bin_scaling, out, B, NB);
    } else {
        const int threads = 256;
        const int rows_per_block = threads / 32;
        const int blocks = (B + rows_per_block - 1) / rows_per_block;
        confcal_kernel_gen<<<blocks, threads>>>(x, bin_scaling, out, B, D, NB);
    }
}

// round 14
// speedup vs baseline: 1.1648x; 1.1648x over previous
#include <cuda_runtime.h>
#include <math.h>
#include <stdint.h>

// ConfidenceCalibration: softmax over bins sums to 1 =>
//   final = clip(sigmoid(mean(x,-1)) * bin_scaling[bucketize(base)], 0, 1)
// Pure HBM read of x (128 MB) + tiny epilogue.
//
// R13 -> R14 (final): CTA-size curve is unimodal, peak at 128 threads:
// DRAM% 60.8 (64thr) / 71.4 (128thr) / 70.4 (256thr) / 57.6 (512thr).
// Small CTAs pay churn+tail, large CTAs pay synchronized LDG-burst
// contention in the L1tex queue; 128 is the crossing point. This round is
// the rigor.md confirmation re-bench of the measured-best R12 config
// (kernel 24.32us, HBM 5.65TB/s). All other levers (MLP 4/8, persistent
// grid, bulk-TMA staging, .cs/.nc.L2::256B, f32x2 packing) were probed and
// plateau or regress — the kernel is at the platform's streaming ceiling.

__device__ __forceinline__ uint64_t pack_f32x2(float lo, float hi) {
    uint64_t r;
    asm("mov.b64 %0, {%1, %2};" : "=l"(r) : "f"(lo), "f"(hi));
    return r;
}
__device__ __forceinline__ uint64_t add_f32x2(uint64_t a, uint64_t b) {
    uint64_t r;
    asm("add.rn.f32x2 %0, %1, %2;" : "=l"(r) : "l"(a), "l"(b));
    return r;
}
__device__ __forceinline__ float hsum_f32x2(uint64_t a) {
    float lo, hi;
    asm("mov.b64 {%0, %1}, %2;" : "=f"(lo), "=f"(hi) : "l"(a));
    return lo + hi;
}

__device__ __forceinline__ float warp_reduce_sum(float s) {
    #pragma unroll
    for (int o = 16; o; o >>= 1) s += __shfl_xor_sync(0xffffffffu, s, o);
    return s;
}

__device__ __forceinline__ void finalize(float s, float invD, int NB,
                                         const float* __restrict__ bin_scaling,
                                         float* __restrict__ out, int row) {
    float mean = s * invD;
    float base = 1.0f / (1.0f + expf(-mean));
    // searchsorted(linspace(0,1,NB+1), base, 'right') - 1
    int idx = -1;
    for (int i = 0; i <= NB; i++) {
        float bnd = (float)i / (float)NB;
        if (bnd <= base) idx = i; else break;
    }
    float scale = (idx >= 0 && idx < NB) ? bin_scaling[idx] : 0.0f;
    out[row] = fminf(fmaxf(base * scale, 0.0f), 1.0f);
}

// Specialized: D == 1024. One row per warp, 8x LDG.128 front-batched,
// packed f32x2 reduction tree. 128-thread CTAs (measured optimum).
__global__ void __launch_bounds__(128) confcal_kernel_1024(
        const float* __restrict__ x,
        const float* __restrict__ bin_scaling,
        float* __restrict__ out,
        int B, int NB) {
    const int gwarp = (blockIdx.x * blockDim.x + threadIdx.x) >> 5;
    const int lane  = threadIdx.x & 31;
    if (gwarp >= B) return;

    const float4* p = reinterpret_cast<const float4*>(x + (size_t)gwarp * 1024u) + lane;

    // 8 independent streaming loads, all in flight before arithmetic.
    float4 v0 = __ldcs(p + 0 * 32);
    float4 v1 = __ldcs(p + 1 * 32);
    float4 v2 = __ldcs(p + 2 * 32);
    float4 v3 = __ldcs(p + 3 * 32);
    float4 v4 = __ldcs(p + 4 * 32);
    float4 v5 = __ldcs(p + 5 * 32);
    float4 v6 = __ldcs(p + 6 * 32);
    float4 v7 = __ldcs(p + 7 * 32);

    // Packed f32x2 pairwise tree: 16 packs, 15 packed adds, 1 scalar add.
    uint64_t p0 = add_f32x2(pack_f32x2(v0.x, v0.y), pack_f32x2(v0.z, v0.w));
    uint64_t p1 = add_f32x2(pack_f32x2(v1.x, v1.y), pack_f32x2(v1.z, v1.w));
    uint64_t p2 = add_f32x2(pack_f32x2(v2.x, v2.y), pack_f32x2(v2.z, v2.w));
    uint64_t p3 = add_f32x2(pack_f32x2(v3.x, v3.y), pack_f32x2(v3.z, v3.w));
    uint64_t p4 = add_f32x2(pack_f32x2(v4.x, v4.y), pack_f32x2(v4.z, v4.w));
    uint64_t p5 = add_f32x2(pack_f32x2(v5.x, v5.y), pack_f32x2(v5.z, v5.w));
    uint64_t p6 = add_f32x2(pack_f32x2(v6.x, v6.y), pack_f32x2(v6.z, v6.w));
    uint64_t p7 = add_f32x2(pack_f32x2(v7.x, v7.y), pack_f32x2(v7.z, v7.w));
    uint64_t q0 = add_f32x2(add_f32x2(p0, p1), add_f32x2(p2, p3));
    uint64_t q1 = add_f32x2(add_f32x2(p4, p5), add_f32x2(p6, p7));
    float s = hsum_f32x2(add_f32x2(q0, q1));

    s = warp_reduce_sum(s);
    if (lane == 0) finalize(s, 1.0f / 1024.0f, NB, bin_scaling, out, gwarp);
}

// Generic fallback for other D
__global__ void confcal_kernel_gen(const float* __restrict__ x,
                                   const float* __restrict__ bin_scaling,
                                   float* __restrict__ out,
                                   int B, int D, int NB) {
    const int gwarp = (blockIdx.x * blockDim.x + threadIdx.x) >> 5;
    const int lane  = threadIdx.x & 31;
    if (gwarp >= B) return;

    const float* rowp = x + (size_t)gwarp * (size_t)D;
    const int nvec = D >> 2;
    const float4* row4 = reinterpret_cast<const float4*>(rowp);

    float s = 0.0f;
    #pragma unroll 8
    for (int i = lane; i < nvec; i += 32) {
        float4 v = __ldcs(row4 + i);
        s += (v.x + v.y) + (v.z + v.w);
    }
    for (int i = (nvec << 2) + lane; i < D; i += 32) s += rowp[i];

    s = warp_reduce_sum(s);
    if (lane == 0) finalize(s, 1.0f / (float)D, NB, bin_scaling, out, gwarp);
}

extern "C" void kernel_launch(void* const* d_in, const int* in_sizes, int n_in,
                              void* d_out, int out_size) {
    const float* x           = (const float*)d_in[0];
    const float* bin_scaling = (const float*)d_in[7];
    float* out = (float*)d_out;

    const int B  = out_size;            // 32768
    const int D  = in_sizes[0] / B;     // 1024
    const int NB = in_sizes[7];         // 15

    if (D == 1024 && (((uintptr_t)x) & 15u) == 0) {
        const int threads = 128;        // 4 warps = 4 rows per block (optimum)
        const int rows_per_block = threads / 32;
        const int blocks = (B + rows_per_block - 1) / rows_per_block;   // 8192
        confcal_kernel_1024<<<blocks, threads>>>(x, bin_scaling, out, B, NB);
    } else {
        const int threads = 256;
        const int rows_per_block = threads / 32;
        const int blocks = (B + rows_per_block - 1) / rows_per_block;
        confcal_kernel_gen<<<blocks, threads>>>(x, bin_scaling, out, B, D, NB);
    }
}